// round 13
// baseline (speedup 1.0000x reference)
#include <cuda_runtime.h>
#include <cuda_fp16.h>
#include <cstdint>
#include <cstddef>

// ---------------------------------------------------------------------------
// Problem constants (fixed shapes)
// ---------------------------------------------------------------------------
#define N0 200000
#define N1 100000
#define N2 50000
#define E0 1600000
#define E1 800000
#define F_IN 128
#define F_H  256
#define F_OUT 64

#define G1SPLIT 70000        // gather1 nodes on side stream
#define TILES_B1 391         // B row-tiles in first half (rows 0..50047)
#define TILES_N1 782         // ceil(100000/128)
#define TILES_N2 391         // ceil(50000/128)

// ---------------------------------------------------------------------------
// Scratch (device globals; no allocation allowed)
// ---------------------------------------------------------------------------
__device__ __half g_xh[(size_t)N0 * F_IN];        // x in fp16 (51.2 MB)
__device__ __half g_m0[(size_t)N1 * F_IN];        // layer-1 neighbor means
__device__ __half g_p1[(size_t)N1 * F_H];         // x @ Ws1 + b1
__device__ __half g_h1[(size_t)N1 * F_H];         // hidden activations
__device__ __half g_z2[(size_t)N1 * F_OUT];       // h1 @ Wn2
__device__ int    g_rp0[N1 + 1];
__device__ int    g_rp1[N2 + 1];
__device__ __half g_Bt1s[(size_t)F_H * F_IN];
__device__ __half g_Bt1n[(size_t)F_H * F_IN];
__device__ __half g_Bt2s[(size_t)F_OUT * F_H];
__device__ __half g_Bt2n[(size_t)F_OUT * F_H];
__device__ float  g_zeros[F_H];

// ---------------------------------------------------------------------------
// Helpers
// ---------------------------------------------------------------------------
__device__ __forceinline__ void mma_f16(float* d, const uint32_t* a,
                                        const uint32_t* b, const float* c) {
    asm("mma.sync.aligned.m16n8k16.row.col.f32.f16.f16.f32 "
        "{%0,%1,%2,%3}, {%4,%5,%6,%7}, {%8,%9}, {%10,%11,%12,%13};"
        : "=f"(d[0]), "=f"(d[1]), "=f"(d[2]), "=f"(d[3])
        : "r"(a[0]), "r"(a[1]), "r"(a[2]), "r"(a[3]),
          "r"(b[0]), "r"(b[1]),
          "f"(c[0]), "f"(c[1]), "f"(c[2]), "f"(c[3]));
}
__device__ __forceinline__ void ldsm_x4(uint32_t& r0, uint32_t& r1,
                                        uint32_t& r2, uint32_t& r3,
                                        uint32_t saddr) {
    asm volatile("ldmatrix.sync.aligned.m8n8.x4.shared.b16 {%0,%1,%2,%3}, [%4];"
                 : "=r"(r0), "=r"(r1), "=r"(r2), "=r"(r3) : "r"(saddr));
}
__device__ __forceinline__ uint32_t packh2(float x, float y) {
    __half2 h = __floats2half2_rn(x, y);
    return *(uint32_t*)&h;
}

// ---------------------------------------------------------------------------
// prepA / prepB / xh-convert
// ---------------------------------------------------------------------------
#define NB_RP0 ((E0 + 255) / 256)
#define NB_RP1 ((E1 + 255) / 256)
__global__ void __launch_bounds__(256)
prepA_kernel(const int* __restrict__ dst0,
             const float* __restrict__ Ws1, const float* __restrict__ Wn1,
             int* __restrict__ rp0,
             __half* __restrict__ Bt1s, __half* __restrict__ Bt1n) {
    int b = blockIdx.x, tid = threadIdx.x;
    if (b < NB_RP0) {
        int i = b * 256 + tid;
        if (i < E0) {
            int d = dst0[i];
            int prev = (i == 0) ? -1 : dst0[i - 1];
            for (int n = prev + 1; n <= d; ++n) rp0[n] = i;
            if (i == E0 - 1)
                for (int n = d + 1; n <= N1; ++n) rp0[n] = E0;
        }
    } else if (b < NB_RP0 + 256) {
        int n = b - NB_RP0;
        if (tid < F_IN) Bt1s[(size_t)n * F_IN + tid] =
            __float2half(Ws1[(size_t)tid * F_H + n]);
    } else {
        int n = b - (NB_RP0 + 256);
        if (tid < F_IN) Bt1n[(size_t)n * F_IN + tid] =
            __float2half(Wn1[(size_t)tid * F_H + n]);
    }
}

__global__ void __launch_bounds__(256)
prepB_kernel(const int* __restrict__ dst1,
             const float* __restrict__ Ws2, const float* __restrict__ Wn2,
             int* __restrict__ rp1,
             __half* __restrict__ Bt2s, __half* __restrict__ Bt2n) {
    int b = blockIdx.x, tid = threadIdx.x;
    if (b < NB_RP1) {
        int i = b * 256 + tid;
        if (i < E1) {
            int d = dst1[i];
            int prev = (i == 0) ? -1 : dst1[i - 1];
            for (int n = prev + 1; n <= d; ++n) rp1[n] = i;
            if (i == E1 - 1)
                for (int n = d + 1; n <= N2; ++n) rp1[n] = E1;
        }
    } else if (b < NB_RP1 + 64) {
        int n = b - NB_RP1;
        Bt2s[(size_t)n * F_H + tid] = __float2half(Ws2[(size_t)tid * F_OUT + n]);
    } else {
        int n = b - (NB_RP1 + 64);
        Bt2n[(size_t)n * F_H + tid] = __float2half(Wn2[(size_t)tid * F_OUT + n]);
    }
}

__global__ void __launch_bounds__(256)
xh_convert_kernel(const float* __restrict__ x, __half* __restrict__ xh) {
    size_t base = ((size_t)blockIdx.x * 256 + threadIdx.x) * 8;
    float4 v0 = *(const float4*)(x + base);
    float4 v1 = *(const float4*)(x + base + 4);
    uint4 o;
    o.x = packh2(v0.x, v0.y); o.y = packh2(v0.z, v0.w);
    o.z = packh2(v1.x, v1.y); o.w = packh2(v1.z, v1.w);
    *(uint4*)(xh + base) = o;
}

// ---------------------------------------------------------------------------
// gather1 over node range [nodeBase, nodeEnd): fp16 rows (16 uint4 lanes),
// 4-edge unroll, fp32 accumulate, fp16 out.
// ---------------------------------------------------------------------------
__global__ void __launch_bounds__(256)
gather1_kernel(const uint4* __restrict__ feat, const int* __restrict__ src,
               const int* __restrict__ rp, uint4* __restrict__ out,
               int nodeBase, int nodeEnd) {
    constexpr int V = 16;
    int t = blockIdx.x * 256 + threadIdx.x;
    int gid = nodeBase + t / V;
    int lane = t % V;
    if (gid >= nodeEnd) return;
    int s = rp[gid], e = rp[gid + 1];
    float acc[8];
#pragma unroll
    for (int j = 0; j < 8; ++j) acc[j] = 0.f;
    int i = s;
    for (; i + 3 < e; i += 4) {
        int s0 = src[i], s1 = src[i + 1], s2 = src[i + 2], s3 = src[i + 3];
        uint4 u0 = feat[(size_t)s0 * V + lane];
        uint4 u1 = feat[(size_t)s1 * V + lane];
        uint4 u2 = feat[(size_t)s2 * V + lane];
        uint4 u3 = feat[(size_t)s3 * V + lane];
        const __half2* h0 = (const __half2*)&u0;
        const __half2* h1 = (const __half2*)&u1;
        const __half2* h2 = (const __half2*)&u2;
        const __half2* h3 = (const __half2*)&u3;
#pragma unroll
        for (int j = 0; j < 4; ++j) {
            float2 f0 = __half22float2(h0[j]);
            float2 f1 = __half22float2(h1[j]);
            float2 f2 = __half22float2(h2[j]);
            float2 f3 = __half22float2(h3[j]);
            acc[2 * j]     += (f0.x + f1.x) + (f2.x + f3.x);
            acc[2 * j + 1] += (f0.y + f1.y) + (f2.y + f3.y);
        }
    }
    for (; i < e; ++i) {
        uint4 u = feat[(size_t)src[i] * V + lane];
        const __half2* h = (const __half2*)&u;
#pragma unroll
        for (int j = 0; j < 4; ++j) {
            float2 f = __half22float2(h[j]);
            acc[2 * j] += f.x;
            acc[2 * j + 1] += f.y;
        }
    }
    float inv = 1.f / fmaxf((float)(e - s), 1.f);
    uint4 o;
    o.x = packh2(acc[0] * inv, acc[1] * inv);
    o.y = packh2(acc[2] * inv, acc[3] * inv);
    o.z = packh2(acc[4] * inv, acc[5] * inv);
    o.w = packh2(acc[6] * inv, acc[7] * inv);
    out[(size_t)gid * V + lane] = o;
}

// ---------------------------------------------------------------------------
// gather2 fused: out += mean(z2 rows over edges)
// ---------------------------------------------------------------------------
__global__ void __launch_bounds__(256)
gather2_fused_kernel(const uint2* __restrict__ feat, const int* __restrict__ src,
                     const int* __restrict__ rp, float4* __restrict__ out) {
    constexpr int V = 16;
    int t = blockIdx.x * 256 + threadIdx.x;
    int gid = t / V;
    int lane = t % V;
    if (gid >= N2) return;
    int s = rp[gid], e = rp[gid + 1];
    float4 acc = make_float4(0.f, 0.f, 0.f, 0.f);
    int i = s;
    for (; i + 1 < e; i += 2) {
        uint2 u0 = feat[(size_t)src[i] * V + lane];
        uint2 u1 = feat[(size_t)src[i + 1] * V + lane];
        float2 a0 = __half22float2(*(__half2*)&u0.x);
        float2 b0 = __half22float2(*(__half2*)&u0.y);
        float2 a1 = __half22float2(*(__half2*)&u1.x);
        float2 b1 = __half22float2(*(__half2*)&u1.y);
        acc.x += a0.x + a1.x; acc.y += a0.y + a1.y;
        acc.z += b0.x + b1.x; acc.w += b0.y + b1.y;
    }
    if (i < e) {
        uint2 u = feat[(size_t)src[i] * V + lane];
        float2 a = __half22float2(*(__half2*)&u.x);
        float2 b = __half22float2(*(__half2*)&u.y);
        acc.x += a.x; acc.y += a.y; acc.z += b.x; acc.w += b.y;
    }
    float inv = 1.f / fmaxf((float)(e - s), 1.f);
    float4 cur = out[(size_t)gid * V + lane];
    cur.x += acc.x * inv; cur.y += acc.y * inv;
    cur.z += acc.z * inv; cur.w += acc.w * inv;
    out[(size_t)gid * V + lane] = cur;
}

// ---------------------------------------------------------------------------
// fp16 m16n8k16 mma.sync GEMM with row-tile offset (bmOff, in 128-row tiles)
// ---------------------------------------------------------------------------
template <int BN, int WARPS_M, int WARPS_N, int K, int NTOT, bool RELU,
          bool ADDIN, bool A_HALF, bool OUT_HALF>
__global__ void __launch_bounds__(256, 2)
gemm_kernel(const void* __restrict__ Av, const __half* __restrict__ Bt,
            const float* __restrict__ bias, const __half* __restrict__ addin,
            void* __restrict__ Cv, int M, int bmOff) {
    constexpr int BM = 128;
    constexpr int BK = 32;
    constexpr int ST = 20;
    constexpr int KT = K / BK;
    constexpr int WM = BM / WARPS_M;
    constexpr int WN = BN / WARPS_N;
    constexpr int WM16 = WM / 16;
    constexpr int WN8 = WN / 8;
    constexpr int A_ST_SZ = BM * ST;
    constexpr int B_ST_SZ = BN * ST;
    constexpr int APT_F = BM * BK / (4 * 256);
    constexpr int APT_H = BM * BK / (8 * 256);
    constexpr int BPT_H = BN * BK / (8 * 256);

    extern __shared__ uint32_t smu[];
    uint32_t* Asm = smu;
    uint32_t* Bsm = smu + 2 * A_ST_SZ;
    const uint32_t smaddr = (uint32_t)__cvta_generic_to_shared(smu);

    const int bm = (blockIdx.x + bmOff) * BM;
    const int bn = blockIdx.y * BN;
    const int tid = threadIdx.x;
    const int lane = tid & 31;
    const int wid = tid >> 5;
    const int wm = wid / WARPS_N;
    const int wn = wid % WARPS_N;

    float acc[WM16][WN8][4];
#pragma unroll
    for (int i = 0; i < WM16; ++i)
#pragma unroll
        for (int j = 0; j < WN8; ++j)
#pragma unroll
            for (int q = 0; q < 4; ++q) acc[i][j][q] = 0.f;

    float4 raf[A_HALF ? 1 : APT_F];
    uint4 rah[A_HALF ? APT_H : 1];
    uint4 rb[BPT_H];

    auto load_chunk = [&](int c) {
        const int kb = c * BK;
        if (!A_HALF) {
            const float* A = (const float*)Av;
#pragma unroll
            for (int i = 0; i < APT_F; ++i) {
                int idx = tid + i * 256;
                int r = idx >> 3, c4 = idx & 7;
                int gr = bm + r;
                raf[i] = (gr < M)
                    ? *(const float4*)(A + (size_t)gr * K + kb + c4 * 4)
                    : make_float4(0.f, 0.f, 0.f, 0.f);
            }
        } else {
            const __half* A = (const __half*)Av;
#pragma unroll
            for (int i = 0; i < APT_H; ++i) {
                int idx = tid + i * 256;
                int r = idx >> 2, c8 = idx & 3;
                int gr = bm + r;
                rah[i] = (gr < M)
                    ? *(const uint4*)(A + (size_t)gr * K + kb + c8 * 8)
                    : make_uint4(0u, 0u, 0u, 0u);
            }
        }
#pragma unroll
        for (int i = 0; i < BPT_H; ++i) {
            int idx = tid + i * 256;
            int r = idx >> 2, c8 = idx & 3;
            rb[i] = *(const uint4*)(Bt + (size_t)(bn + r) * K + kb + c8 * 8);
        }
    };

    auto sts_chunk = [&](int s) {
        uint32_t* as = Asm + s * A_ST_SZ;
        uint32_t* bs = Bsm + s * B_ST_SZ;
        if (!A_HALF) {
#pragma unroll
            for (int i = 0; i < APT_F; ++i) {
                int idx = tid + i * 256;
                int r = idx >> 3, c4 = idx & 7;
                uint2 h;
                h.x = packh2(raf[i].x, raf[i].y);
                h.y = packh2(raf[i].z, raf[i].w);
                *(uint2*)(as + r * ST + c4 * 2) = h;
            }
        } else {
#pragma unroll
            for (int i = 0; i < APT_H; ++i) {
                int idx = tid + i * 256;
                int r = idx >> 2, c8 = idx & 3;
                *(uint4*)(as + r * ST + c8 * 4) = rah[i];
            }
        }
#pragma unroll
        for (int i = 0; i < BPT_H; ++i) {
            int idx = tid + i * 256;
            int r = idx >> 2, c8 = idx & 3;
            *(uint4*)(bs + r * ST + c8 * 4) = rb[i];
        }
    };

    const int a_lrow = lane & 15;
    const int a_lcol = (lane >> 4) << 2;
    const int b_lrow = (lane & 7) + ((lane >> 4) << 3);
    const int b_lcol = ((lane >> 3) & 1) << 2;

    auto compute = [&](int s) {
        const uint32_t a_s = smaddr + (s * A_ST_SZ) * 4;
        const uint32_t b_s = smaddr + (2 * A_ST_SZ + s * B_ST_SZ) * 4;
#pragma unroll
        for (int ks = 0; ks < 2; ++ks) {
            const int kk2 = ks * 8;
            uint32_t af[WM16][4];
#pragma unroll
            for (int mi = 0; mi < WM16; ++mi) {
                uint32_t addr = a_s +
                    (((wm * WM + mi * 16 + a_lrow) * ST) + kk2 + a_lcol) * 4;
                ldsm_x4(af[mi][0], af[mi][1], af[mi][2], af[mi][3], addr);
            }
            uint32_t bf[WN8][2];
#pragma unroll
            for (int p = 0; p < WN8 / 2; ++p) {
                uint32_t addr = b_s +
                    (((wn * WN + p * 16 + b_lrow) * ST) + kk2 + b_lcol) * 4;
                ldsm_x4(bf[2 * p][0], bf[2 * p][1],
                        bf[2 * p + 1][0], bf[2 * p + 1][1], addr);
            }
#pragma unroll
            for (int mi = 0; mi < WM16; ++mi)
#pragma unroll
                for (int ni = 0; ni < WN8; ++ni)
                    mma_f16(acc[mi][ni], af[mi], bf[ni], acc[mi][ni]);
        }
    };

    load_chunk(0);
    sts_chunk(0);
    __syncthreads();

#pragma unroll 1
    for (int c = 0; c < KT; ++c) {
        if (c + 1 < KT) load_chunk(c + 1);
        compute(c & 1);
        if (c + 1 < KT) {
            sts_chunk((c + 1) & 1);
            __syncthreads();
        }
    }

    const int g2 = lane >> 2;
    const int t2 = lane & 3;
#pragma unroll
    for (int mi = 0; mi < WM16; ++mi) {
        int row0 = bm + wm * WM + mi * 16 + g2;
#pragma unroll
        for (int ni = 0; ni < WN8; ++ni) {
            int col = bn + wn * WN + ni * 8 + 2 * t2;
            float bx = bias[col], by = bias[col + 1];
            float2 v0, v1;
            v0.x = acc[mi][ni][0] + bx; v0.y = acc[mi][ni][1] + by;
            v1.x = acc[mi][ni][2] + bx; v1.y = acc[mi][ni][3] + by;
            if (ADDIN) {
                if (row0 < M) {
                    float2 a0 = __half22float2(
                        *(const __half2*)(addin + (size_t)row0 * NTOT + col));
                    v0.x += a0.x; v0.y += a0.y;
                }
                if (row0 + 8 < M) {
                    float2 a1 = __half22float2(
                        *(const __half2*)(addin + (size_t)(row0 + 8) * NTOT + col));
                    v1.x += a1.x; v1.y += a1.y;
                }
            }
            if (RELU) {
                v0.x = fmaxf(v0.x, 0.f); v0.y = fmaxf(v0.y, 0.f);
                v1.x = fmaxf(v1.x, 0.f); v1.y = fmaxf(v1.y, 0.f);
            }
            if (OUT_HALF) {
                __half* C = (__half*)Cv;
                if (row0 < M)
                    *(__half2*)(C + (size_t)row0 * NTOT + col) =
                        __floats2half2_rn(v0.x, v0.y);
                if (row0 + 8 < M)
                    *(__half2*)(C + (size_t)(row0 + 8) * NTOT + col) =
                        __floats2half2_rn(v1.x, v1.y);
            } else {
                float* C = (float*)Cv;
                if (row0 < M)     *(float2*)(C + (size_t)row0 * NTOT + col) = v0;
                if (row0 + 8 < M) *(float2*)(C + (size_t)(row0 + 8) * NTOT + col) = v1;
            }
        }
    }
}

// ---------------------------------------------------------------------------
// Launch: two-stream DAG with split gather1 and row-split tail
//   prepA
//   fork: s1: xh-cvt -> gather1[0,70k)            main: gemmA -> prepB
//         (main waits cvt) -> gather1[70k,100k)
//   join -> B1 (tiles 0..390)
//   fork: s1: gemmD -> C1 (tiles 0..390)          main: B2 -> C2
//   join -> gather2 += mean(z2)
// ---------------------------------------------------------------------------
extern "C" void kernel_launch(void* const* d_in, const int* in_sizes, int n_in,
                              void* d_out, int out_size) {
    const float* x    = (const float*)d_in[0];
    const int*   src0 = (const int*)d_in[1];
    const int*   dst0 = (const int*)d_in[2];
    const int*   src1 = (const int*)d_in[3];
    const int*   dst1 = (const int*)d_in[4];
    const float* Ws1  = (const float*)d_in[7];
    const float* Wn1  = (const float*)d_in[8];
    const float* b1   = (const float*)d_in[9];
    const float* Ws2  = (const float*)d_in[10];
    const float* Wn2  = (const float*)d_in[11];
    const float* b2   = (const float*)d_in[12];
    float*       out  = (float*)d_out;

    __half *xh, *m0, *p1, *h1, *z2, *Bt1s, *Bt1n, *Bt2s, *Bt2n;
    float *zeros;
    int *rp0, *rp1;
    cudaGetSymbolAddress((void**)&xh,   g_xh);
    cudaGetSymbolAddress((void**)&m0,   g_m0);
    cudaGetSymbolAddress((void**)&p1,   g_p1);
    cudaGetSymbolAddress((void**)&h1,   g_h1);
    cudaGetSymbolAddress((void**)&z2,   g_z2);
    cudaGetSymbolAddress((void**)&rp0,  g_rp0);
    cudaGetSymbolAddress((void**)&rp1,  g_rp1);
    cudaGetSymbolAddress((void**)&Bt1s, g_Bt1s);
    cudaGetSymbolAddress((void**)&Bt1n, g_Bt1n);
    cudaGetSymbolAddress((void**)&Bt2s, g_Bt2s);
    cudaGetSymbolAddress((void**)&Bt2n, g_Bt2n);
    cudaGetSymbolAddress((void**)&zeros, g_zeros);

    static cudaStream_t s1 = nullptr;
    static cudaEvent_t evF1, evCvt, evJ1, evF2, evJ2;
    if (s1 == nullptr) {
        cudaStreamCreateWithFlags(&s1, cudaStreamNonBlocking);
        cudaEventCreateWithFlags(&evF1, cudaEventDisableTiming);
        cudaEventCreateWithFlags(&evCvt, cudaEventDisableTiming);
        cudaEventCreateWithFlags(&evJ1, cudaEventDisableTiming);
        cudaEventCreateWithFlags(&evF2, cudaEventDisableTiming);
        cudaEventCreateWithFlags(&evJ2, cudaEventDisableTiming);
    }

    constexpr int SMEM_128 = 2 * (128 * 20 + 128 * 20) * 4;  // 40960
    constexpr int SMEM_64  = 2 * (128 * 20 + 64 * 20) * 4;   // 30720

    // --- 1. prepA ---
    prepA_kernel<<<NB_RP0 + 512, 256>>>(dst0, Ws1, Wn1, rp0, Bt1s, Bt1n);

    // --- 2. fork ---
    cudaEventRecord(evF1, 0);
    cudaStreamWaitEvent(s1, evF1, 0);

    // s1: xh convert -> gather1 head [0, G1SPLIT)
    xh_convert_kernel<<<N0 * F_IN / 8 / 256, 256, 0, s1>>>(x, xh);
    cudaEventRecord(evCvt, s1);
    gather1_kernel<<<(G1SPLIT * 16 + 255) / 256, 256, 0, s1>>>(
        (const uint4*)xh, src0, rp0, (uint4*)m0, 0, G1SPLIT);
    cudaEventRecord(evJ1, s1);

    // main: gemmA (x fp32 -> p1), prepB, then gather1 tail [G1SPLIT, N1)
    {
        dim3 grid(TILES_N1, F_H / 128);
        gemm_kernel<128, 2, 4, F_IN, F_H, false, false, false, true>
            <<<grid, 256, SMEM_128>>>(x, Bt1s, b1, nullptr, p1, N1, 0);
    }
    prepB_kernel<<<NB_RP1 + 128, 256>>>(dst1, Ws2, Wn2, rp1, Bt2s, Bt2n);
    cudaStreamWaitEvent(0, evCvt, 0);
    gather1_kernel<<<((N1 - G1SPLIT) * 16 + 255) / 256, 256>>>(
        (const uint4*)xh, src0, rp0, (uint4*)m0, G1SPLIT, N1);
    cudaStreamWaitEvent(0, evJ1, 0);

    // --- 3. B1: h1 rows 0..50047 = relu(m0 @ Wn1 + p1) ---
    {
        dim3 grid(TILES_B1, F_H / 128);
        gemm_kernel<128, 2, 4, F_IN, F_H, true, true, true, true>
            <<<grid, 256, SMEM_128>>>(m0, Bt1n, zeros, p1, h1, N1, 0);
    }

    // --- 4. fork: s1: gemmD -> C1 ; main: B2 -> C2 ---
    cudaEventRecord(evF2, 0);
    cudaStreamWaitEvent(s1, evF2, 0);
    {
        dim3 grid(TILES_N2, 1);
        gemm_kernel<64, 4, 2, F_H, F_OUT, false, false, true, false>
            <<<grid, 256, SMEM_64, s1>>>(h1, Bt2s, b2, nullptr, out, N2, 0);
        gemm_kernel<64, 4, 2, F_H, F_OUT, false, false, true, true>
            <<<grid, 256, SMEM_64, s1>>>(h1, Bt2n, zeros, nullptr, z2, N1, 0);
    }
    cudaEventRecord(evJ2, s1);

    {
        dim3 gridB2(TILES_N1 - TILES_B1, F_H / 128);
        gemm_kernel<128, 2, 4, F_IN, F_H, true, true, true, true>
            <<<gridB2, 256, SMEM_128>>>(m0, Bt1n, zeros, p1, h1, N1, TILES_B1);
        dim3 gridC2(TILES_N1 - TILES_B1, 1);
        gemm_kernel<64, 4, 2, F_H, F_OUT, false, false, true, true>
            <<<gridC2, 256, SMEM_64>>>(h1, Bt2n, zeros, nullptr, z2, N1, TILES_B1);
    }
    cudaStreamWaitEvent(0, evJ2, 0);

    // --- 5. gather2 fused: out += mean(z2 over edges) ---
    gather2_fused_kernel<<<(N2 * 16 + 255) / 256, 256>>>(
        (const uint2*)z2, src1, rp1, (float4*)out);
}

// round 17
// speedup vs baseline: 1.0091x; 1.0091x over previous
#include <cuda_runtime.h>
#include <cuda_fp16.h>
#include <cstdint>
#include <cstddef>

// ---------------------------------------------------------------------------
// Problem constants (fixed shapes)
// ---------------------------------------------------------------------------
#define N0 200000
#define N1 100000
#define N2 50000
#define E0 1600000
#define E1 800000
#define F_IN 128
#define F_H  256
#define F_OUT 64

#define G1SPLIT 70000        // gather1 nodes on side stream
#define TILES_N1 782         // ceil(100000/128)
#define TILES_N2 391         // ceil(50000/128)

// ---------------------------------------------------------------------------
// Scratch (device globals; no allocation allowed)
// ---------------------------------------------------------------------------
__device__ __half g_xh[(size_t)N0 * F_IN];        // x in fp16 (51.2 MB)
__device__ __half g_m0[(size_t)N1 * F_IN];        // layer-1 neighbor means
__device__ __half g_p1[(size_t)N1 * F_H];         // x @ Ws1 + b1
__device__ __half g_h1[(size_t)N1 * F_H];         // hidden activations
__device__ __half g_z2[(size_t)N1 * F_OUT];       // h1 @ Wn2
__device__ int    g_rp0[N1 + 1];
__device__ int    g_rp1[N2 + 1];
__device__ __half g_Bt1s[(size_t)F_H * F_IN];
__device__ __half g_Bt1n[(size_t)F_H * F_IN];
__device__ __half g_Bt2s[(size_t)F_OUT * F_H];
__device__ __half g_Bt2n[(size_t)F_OUT * F_H];
__device__ float  g_zeros[F_H];

// ---------------------------------------------------------------------------
// Helpers
// ---------------------------------------------------------------------------
__device__ __forceinline__ void mma_f16(float* d, const uint32_t* a,
                                        const uint32_t* b, const float* c) {
    asm("mma.sync.aligned.m16n8k16.row.col.f32.f16.f16.f32 "
        "{%0,%1,%2,%3}, {%4,%5,%6,%7}, {%8,%9}, {%10,%11,%12,%13};"
        : "=f"(d[0]), "=f"(d[1]), "=f"(d[2]), "=f"(d[3])
        : "r"(a[0]), "r"(a[1]), "r"(a[2]), "r"(a[3]),
          "r"(b[0]), "r"(b[1]),
          "f"(c[0]), "f"(c[1]), "f"(c[2]), "f"(c[3]));
}
__device__ __forceinline__ void ldsm_x4(uint32_t& r0, uint32_t& r1,
                                        uint32_t& r2, uint32_t& r3,
                                        uint32_t saddr) {
    asm volatile("ldmatrix.sync.aligned.m8n8.x4.shared.b16 {%0,%1,%2,%3}, [%4];"
                 : "=r"(r0), "=r"(r1), "=r"(r2), "=r"(r3) : "r"(saddr));
}
__device__ __forceinline__ uint32_t packh2(float x, float y) {
    __half2 h = __floats2half2_rn(x, y);
    return *(uint32_t*)&h;
}

// ---------------------------------------------------------------------------
// prepA / prepB / xh-convert
// ---------------------------------------------------------------------------
#define NB_RP0 ((E0 + 255) / 256)
#define NB_RP1 ((E1 + 255) / 256)
__global__ void __launch_bounds__(256)
prepA_kernel(const int* __restrict__ dst0,
             const float* __restrict__ Ws1, const float* __restrict__ Wn1,
             int* __restrict__ rp0,
             __half* __restrict__ Bt1s, __half* __restrict__ Bt1n) {
    int b = blockIdx.x, tid = threadIdx.x;
    if (b < NB_RP0) {
        int i = b * 256 + tid;
        if (i < E0) {
            int d = dst0[i];
            int prev = (i == 0) ? -1 : dst0[i - 1];
            for (int n = prev + 1; n <= d; ++n) rp0[n] = i;
            if (i == E0 - 1)
                for (int n = d + 1; n <= N1; ++n) rp0[n] = E0;
        }
    } else if (b < NB_RP0 + 256) {
        int n = b - NB_RP0;
        if (tid < F_IN) Bt1s[(size_t)n * F_IN + tid] =
            __float2half(Ws1[(size_t)tid * F_H + n]);
    } else {
        int n = b - (NB_RP0 + 256);
        if (tid < F_IN) Bt1n[(size_t)n * F_IN + tid] =
            __float2half(Wn1[(size_t)tid * F_H + n]);
    }
}

__global__ void __launch_bounds__(256)
prepB_kernel(const int* __restrict__ dst1,
             const float* __restrict__ Ws2, const float* __restrict__ Wn2,
             int* __restrict__ rp1,
             __half* __restrict__ Bt2s, __half* __restrict__ Bt2n) {
    int b = blockIdx.x, tid = threadIdx.x;
    if (b < NB_RP1) {
        int i = b * 256 + tid;
        if (i < E1) {
            int d = dst1[i];
            int prev = (i == 0) ? -1 : dst1[i - 1];
            for (int n = prev + 1; n <= d; ++n) rp1[n] = i;
            if (i == E1 - 1)
                for (int n = d + 1; n <= N2; ++n) rp1[n] = E1;
        }
    } else if (b < NB_RP1 + 64) {
        int n = b - NB_RP1;
        Bt2s[(size_t)n * F_H + tid] = __float2half(Ws2[(size_t)tid * F_OUT + n]);
    } else {
        int n = b - (NB_RP1 + 64);
        Bt2n[(size_t)n * F_H + tid] = __float2half(Wn2[(size_t)tid * F_OUT + n]);
    }
}

__global__ void __launch_bounds__(256)
xh_convert_kernel(const float* __restrict__ x, __half* __restrict__ xh) {
    size_t base = ((size_t)blockIdx.x * 256 + threadIdx.x) * 8;
    float4 v0 = *(const float4*)(x + base);
    float4 v1 = *(const float4*)(x + base + 4);
    uint4 o;
    o.x = packh2(v0.x, v0.y); o.y = packh2(v0.z, v0.w);
    o.z = packh2(v1.x, v1.y); o.w = packh2(v1.z, v1.w);
    *(uint4*)(xh + base) = o;
}

// ---------------------------------------------------------------------------
// gather1 over node range [nodeBase, nodeEnd): fp16 rows (16 uint4 lanes),
// 8-edge unroll (MLP=8), fp32 accumulate, fp16 out.
// ---------------------------------------------------------------------------
__global__ void __launch_bounds__(256)
gather1_kernel(const uint4* __restrict__ feat, const int* __restrict__ src,
               const int* __restrict__ rp, uint4* __restrict__ out,
               int nodeBase, int nodeEnd) {
    constexpr int V = 16;
    int t = blockIdx.x * 256 + threadIdx.x;
    int gid = nodeBase + t / V;
    int lane = t % V;
    if (gid >= nodeEnd) return;
    int s = rp[gid], e = rp[gid + 1];
    float acc[8];
#pragma unroll
    for (int j = 0; j < 8; ++j) acc[j] = 0.f;
    int i = s;
    for (; i + 7 < e; i += 8) {
        uint4 u[8];
#pragma unroll
        for (int q = 0; q < 8; ++q)
            u[q] = feat[(size_t)src[i + q] * V + lane];
#pragma unroll
        for (int q = 0; q < 8; ++q) {
            const __half2* h = (const __half2*)&u[q];
#pragma unroll
            for (int j = 0; j < 4; ++j) {
                float2 f = __half22float2(h[j]);
                acc[2 * j] += f.x;
                acc[2 * j + 1] += f.y;
            }
        }
    }
    for (; i + 1 < e; i += 2) {
        uint4 u0 = feat[(size_t)src[i] * V + lane];
        uint4 u1 = feat[(size_t)src[i + 1] * V + lane];
        const __half2* h0 = (const __half2*)&u0;
        const __half2* h1 = (const __half2*)&u1;
#pragma unroll
        for (int j = 0; j < 4; ++j) {
            float2 f0 = __half22float2(h0[j]);
            float2 f1 = __half22float2(h1[j]);
            acc[2 * j] += f0.x + f1.x;
            acc[2 * j + 1] += f0.y + f1.y;
        }
    }
    if (i < e) {
        uint4 u = feat[(size_t)src[i] * V + lane];
        const __half2* h = (const __half2*)&u;
#pragma unroll
        for (int j = 0; j < 4; ++j) {
            float2 f = __half22float2(h[j]);
            acc[2 * j] += f.x;
            acc[2 * j + 1] += f.y;
        }
    }
    float inv = 1.f / fmaxf((float)(e - s), 1.f);
    uint4 o;
    o.x = packh2(acc[0] * inv, acc[1] * inv);
    o.y = packh2(acc[2] * inv, acc[3] * inv);
    o.z = packh2(acc[4] * inv, acc[5] * inv);
    o.w = packh2(acc[6] * inv, acc[7] * inv);
    out[(size_t)gid * V + lane] = o;
}

// ---------------------------------------------------------------------------
// gather2 fused: out += mean(z2 rows over edges), 4-edge unroll
// ---------------------------------------------------------------------------
__global__ void __launch_bounds__(256)
gather2_fused_kernel(const uint2* __restrict__ feat, const int* __restrict__ src,
                     const int* __restrict__ rp, float4* __restrict__ out) {
    constexpr int V = 16;
    int t = blockIdx.x * 256 + threadIdx.x;
    int gid = t / V;
    int lane = t % V;
    if (gid >= N2) return;
    int s = rp[gid], e = rp[gid + 1];
    float4 acc = make_float4(0.f, 0.f, 0.f, 0.f);
    int i = s;
    for (; i + 3 < e; i += 4) {
        uint2 u[4];
#pragma unroll
        for (int q = 0; q < 4; ++q)
            u[q] = feat[(size_t)src[i + q] * V + lane];
#pragma unroll
        for (int q = 0; q < 4; ++q) {
            float2 a = __half22float2(*(__half2*)&u[q].x);
            float2 b = __half22float2(*(__half2*)&u[q].y);
            acc.x += a.x; acc.y += a.y; acc.z += b.x; acc.w += b.y;
        }
    }
    for (; i < e; ++i) {
        uint2 u = feat[(size_t)src[i] * V + lane];
        float2 a = __half22float2(*(__half2*)&u.x);
        float2 b = __half22float2(*(__half2*)&u.y);
        acc.x += a.x; acc.y += a.y; acc.z += b.x; acc.w += b.y;
    }
    float inv = 1.f / fmaxf((float)(e - s), 1.f);
    float4 cur = out[(size_t)gid * V + lane];
    cur.x += acc.x * inv; cur.y += acc.y * inv;
    cur.z += acc.z * inv; cur.w += acc.w * inv;
    out[(size_t)gid * V + lane] = cur;
}

// ---------------------------------------------------------------------------
// fp16 m16n8k16 mma.sync GEMM (ldmatrix fragment loads)
// ---------------------------------------------------------------------------
template <int BN, int WARPS_M, int WARPS_N, int K, int NTOT, bool RELU,
          bool ADDIN, bool A_HALF, bool OUT_HALF>
__global__ void __launch_bounds__(256, 2)
gemm_kernel(const void* __restrict__ Av, const __half* __restrict__ Bt,
            const float* __restrict__ bias, const __half* __restrict__ addin,
            void* __restrict__ Cv, int M) {
    constexpr int BM = 128;
    constexpr int BK = 32;
    constexpr int ST = 20;
    constexpr int KT = K / BK;
    constexpr int WM = BM / WARPS_M;
    constexpr int WN = BN / WARPS_N;
    constexpr int WM16 = WM / 16;
    constexpr int WN8 = WN / 8;
    constexpr int A_ST_SZ = BM * ST;
    constexpr int B_ST_SZ = BN * ST;
    constexpr int APT_F = BM * BK / (4 * 256);
    constexpr int APT_H = BM * BK / (8 * 256);
    constexpr int BPT_H = BN * BK / (8 * 256);

    extern __shared__ uint32_t smu[];
    uint32_t* Asm = smu;
    uint32_t* Bsm = smu + 2 * A_ST_SZ;
    const uint32_t smaddr = (uint32_t)__cvta_generic_to_shared(smu);

    const int bm = blockIdx.x * BM;
    const int bn = blockIdx.y * BN;
    const int tid = threadIdx.x;
    const int lane = tid & 31;
    const int wid = tid >> 5;
    const int wm = wid / WARPS_N;
    const int wn = wid % WARPS_N;

    float acc[WM16][WN8][4];
#pragma unroll
    for (int i = 0; i < WM16; ++i)
#pragma unroll
        for (int j = 0; j < WN8; ++j)
#pragma unroll
            for (int q = 0; q < 4; ++q) acc[i][j][q] = 0.f;

    float4 raf[A_HALF ? 1 : APT_F];
    uint4 rah[A_HALF ? APT_H : 1];
    uint4 rb[BPT_H];

    auto load_chunk = [&](int c) {
        const int kb = c * BK;
        if (!A_HALF) {
            const float* A = (const float*)Av;
#pragma unroll
            for (int i = 0; i < APT_F; ++i) {
                int idx = tid + i * 256;
                int r = idx >> 3, c4 = idx & 7;
                int gr = bm + r;
                raf[i] = (gr < M)
                    ? *(const float4*)(A + (size_t)gr * K + kb + c4 * 4)
                    : make_float4(0.f, 0.f, 0.f, 0.f);
            }
        } else {
            const __half* A = (const __half*)Av;
#pragma unroll
            for (int i = 0; i < APT_H; ++i) {
                int idx = tid + i * 256;
                int r = idx >> 2, c8 = idx & 3;
                int gr = bm + r;
                rah[i] = (gr < M)
                    ? *(const uint4*)(A + (size_t)gr * K + kb + c8 * 8)
                    : make_uint4(0u, 0u, 0u, 0u);
            }
        }
#pragma unroll
        for (int i = 0; i < BPT_H; ++i) {
            int idx = tid + i * 256;
            int r = idx >> 2, c8 = idx & 3;
            rb[i] = *(const uint4*)(Bt + (size_t)(bn + r) * K + kb + c8 * 8);
        }
    };

    auto sts_chunk = [&](int s) {
        uint32_t* as = Asm + s * A_ST_SZ;
        uint32_t* bs = Bsm + s * B_ST_SZ;
        if (!A_HALF) {
#pragma unroll
            for (int i = 0; i < APT_F; ++i) {
                int idx = tid + i * 256;
                int r = idx >> 3, c4 = idx & 7;
                uint2 h;
                h.x = packh2(raf[i].x, raf[i].y);
                h.y = packh2(raf[i].z, raf[i].w);
                *(uint2*)(as + r * ST + c4 * 2) = h;
            }
        } else {
#pragma unroll
            for (int i = 0; i < APT_H; ++i) {
                int idx = tid + i * 256;
                int r = idx >> 2, c8 = idx & 3;
                *(uint4*)(as + r * ST + c8 * 4) = rah[i];
            }
        }
#pragma unroll
        for (int i = 0; i < BPT_H; ++i) {
            int idx = tid + i * 256;
            int r = idx >> 2, c8 = idx & 3;
            *(uint4*)(bs + r * ST + c8 * 4) = rb[i];
        }
    };

    const int a_lrow = lane & 15;
    const int a_lcol = (lane >> 4) << 2;
    const int b_lrow = (lane & 7) + ((lane >> 4) << 3);
    const int b_lcol = ((lane >> 3) & 1) << 2;

    auto compute = [&](int s) {
        const uint32_t a_s = smaddr + (s * A_ST_SZ) * 4;
        const uint32_t b_s = smaddr + (2 * A_ST_SZ + s * B_ST_SZ) * 4;
#pragma unroll
        for (int ks = 0; ks < 2; ++ks) {
            const int kk2 = ks * 8;
            uint32_t af[WM16][4];
#pragma unroll
            for (int mi = 0; mi < WM16; ++mi) {
                uint32_t addr = a_s +
                    (((wm * WM + mi * 16 + a_lrow) * ST) + kk2 + a_lcol) * 4;
                ldsm_x4(af[mi][0], af[mi][1], af[mi][2], af[mi][3], addr);
            }
            uint32_t bf[WN8][2];
#pragma unroll
            for (int p = 0; p < WN8 / 2; ++p) {
                uint32_t addr = b_s +
                    (((wn * WN + p * 16 + b_lrow) * ST) + kk2 + b_lcol) * 4;
                ldsm_x4(bf[2 * p][0], bf[2 * p][1],
                        bf[2 * p + 1][0], bf[2 * p + 1][1], addr);
            }
#pragma unroll
            for (int mi = 0; mi < WM16; ++mi)
#pragma unroll
                for (int ni = 0; ni < WN8; ++ni)
                    mma_f16(acc[mi][ni], af[mi], bf[ni], acc[mi][ni]);
        }
    };

    load_chunk(0);
    sts_chunk(0);
    __syncthreads();

#pragma unroll 1
    for (int c = 0; c < KT; ++c) {
        if (c + 1 < KT) load_chunk(c + 1);
        compute(c & 1);
        if (c + 1 < KT) {
            sts_chunk((c + 1) & 1);
            __syncthreads();
        }
    }

    const int g2 = lane >> 2;
    const int t2 = lane & 3;
#pragma unroll
    for (int mi = 0; mi < WM16; ++mi) {
        int row0 = bm + wm * WM + mi * 16 + g2;
#pragma unroll
        for (int ni = 0; ni < WN8; ++ni) {
            int col = bn + wn * WN + ni * 8 + 2 * t2;
            float bx = bias[col], by = bias[col + 1];
            float2 v0, v1;
            v0.x = acc[mi][ni][0] + bx; v0.y = acc[mi][ni][1] + by;
            v1.x = acc[mi][ni][2] + bx; v1.y = acc[mi][ni][3] + by;
            if (ADDIN) {
                if (row0 < M) {
                    float2 a0 = __half22float2(
                        *(const __half2*)(addin + (size_t)row0 * NTOT + col));
                    v0.x += a0.x; v0.y += a0.y;
                }
                if (row0 + 8 < M) {
                    float2 a1 = __half22float2(
                        *(const __half2*)(addin + (size_t)(row0 + 8) * NTOT + col));
                    v1.x += a1.x; v1.y += a1.y;
                }
            }
            if (RELU) {
                v0.x = fmaxf(v0.x, 0.f); v0.y = fmaxf(v0.y, 0.f);
                v1.x = fmaxf(v1.x, 0.f); v1.y = fmaxf(v1.y, 0.f);
            }
            if (OUT_HALF) {
                __half* C = (__half*)Cv;
                if (row0 < M)
                    *(__half2*)(C + (size_t)row0 * NTOT + col) =
                        __floats2half2_rn(v0.x, v0.y);
                if (row0 + 8 < M)
                    *(__half2*)(C + (size_t)(row0 + 8) * NTOT + col) =
                        __floats2half2_rn(v1.x, v1.y);
            } else {
                float* C = (float*)Cv;
                if (row0 < M)     *(float2*)(C + (size_t)row0 * NTOT + col) = v0;
                if (row0 + 8 < M) *(float2*)(C + (size_t)(row0 + 8) * NTOT + col) = v1;
            }
        }
    }
}

// ---------------------------------------------------------------------------
// Launch: two-stream DAG
//   prepA
//   fork: s1: xh-cvt -> gather1[0,70k)     main: gemmA -> prepB
//         main (after cvt): gather1[70k,100k)
//   join -> B (all 782 tiles)
//   fork: s1: gemmD                        main: C
//   join -> gather2 += mean(z2)
// ---------------------------------------------------------------------------
extern "C" void kernel_launch(void* const* d_in, const int* in_sizes, int n_in,
                              void* d_out, int out_size) {
    const float* x    = (const float*)d_in[0];
    const int*   src0 = (const int*)d_in[1];
    const int*   dst0 = (const int*)d_in[2];
    const int*   src1 = (const int*)d_in[3];
    const int*   dst1 = (const int*)d_in[4];
    const float* Ws1  = (const float*)d_in[7];
    const float* Wn1  = (const float*)d_in[8];
    const float* b1   = (const float*)d_in[9];
    const float* Ws2  = (const float*)d_in[10];
    const float* Wn2  = (const float*)d_in[11];
    const float* b2   = (const float*)d_in[12];
    float*       out  = (float*)d_out;

    __half *xh, *m0, *p1, *h1, *z2, *Bt1s, *Bt1n, *Bt2s, *Bt2n;
    float *zeros;
    int *rp0, *rp1;
    cudaGetSymbolAddress((void**)&xh,   g_xh);
    cudaGetSymbolAddress((void**)&m0,   g_m0);
    cudaGetSymbolAddress((void**)&p1,   g_p1);
    cudaGetSymbolAddress((void**)&h1,   g_h1);
    cudaGetSymbolAddress((void**)&z2,   g_z2);
    cudaGetSymbolAddress((void**)&rp0,  g_rp0);
    cudaGetSymbolAddress((void**)&rp1,  g_rp1);
    cudaGetSymbolAddress((void**)&Bt1s, g_Bt1s);
    cudaGetSymbolAddress((void**)&Bt1n, g_Bt1n);
    cudaGetSymbolAddress((void**)&Bt2s, g_Bt2s);
    cudaGetSymbolAddress((void**)&Bt2n, g_Bt2n);
    cudaGetSymbolAddress((void**)&zeros, g_zeros);

    static cudaStream_t s1 = nullptr;
    static cudaEvent_t evF1, evCvt, evJ1, evF2, evJ2;
    if (s1 == nullptr) {
        cudaStreamCreateWithFlags(&s1, cudaStreamNonBlocking);
        cudaEventCreateWithFlags(&evF1, cudaEventDisableTiming);
        cudaEventCreateWithFlags(&evCvt, cudaEventDisableTiming);
        cudaEventCreateWithFlags(&evJ1, cudaEventDisableTiming);
        cudaEventCreateWithFlags(&evF2, cudaEventDisableTiming);
        cudaEventCreateWithFlags(&evJ2, cudaEventDisableTiming);
    }

    constexpr int SMEM_128 = 2 * (128 * 20 + 128 * 20) * 4;  // 40960
    constexpr int SMEM_64  = 2 * (128 * 20 + 64 * 20) * 4;   // 30720

    // --- 1. prepA ---
    prepA_kernel<<<NB_RP0 + 512, 256>>>(dst0, Ws1, Wn1, rp0, Bt1s, Bt1n);

    // --- 2. fork ---
    cudaEventRecord(evF1, 0);
    cudaStreamWaitEvent(s1, evF1, 0);

    // s1: xh convert -> gather1 head [0, G1SPLIT)
    xh_convert_kernel<<<N0 * F_IN / 8 / 256, 256, 0, s1>>>(x, xh);
    cudaEventRecord(evCvt, s1);
    gather1_kernel<<<(G1SPLIT * 16 + 255) / 256, 256, 0, s1>>>(
        (const uint4*)xh, src0, rp0, (uint4*)m0, 0, G1SPLIT);
    cudaEventRecord(evJ1, s1);

    // main: gemmA (x fp32 -> p1), prepB, then gather1 tail [G1SPLIT, N1)
    {
        dim3 grid(TILES_N1, F_H / 128);
        gemm_kernel<128, 2, 4, F_IN, F_H, false, false, false, true>
            <<<grid, 256, SMEM_128>>>(x, Bt1s, b1, nullptr, p1, N1);
    }
    prepB_kernel<<<NB_RP1 + 128, 256>>>(dst1, Ws2, Wn2, rp1, Bt2s, Bt2n);
    cudaStreamWaitEvent(0, evCvt, 0);
    gather1_kernel<<<((N1 - G1SPLIT) * 16 + 255) / 256, 256>>>(
        (const uint4*)xh, src0, rp0, (uint4*)m0, G1SPLIT, N1);
    cudaStreamWaitEvent(0, evJ1, 0);

    // --- 3. B: h1 = relu(m0 @ Wn1 + p1) ---
    {
        dim3 grid(TILES_N1, F_H / 128);
        gemm_kernel<128, 2, 4, F_IN, F_H, true, true, true, true>
            <<<grid, 256, SMEM_128>>>(m0, Bt1n, zeros, p1, h1, N1);
    }

    // --- 4. fork: gemmD on s1 || C on main ---
    cudaEventRecord(evF2, 0);
    cudaStreamWaitEvent(s1, evF2, 0);
    {
        dim3 grid(TILES_N2, 1);
        gemm_kernel<64, 4, 2, F_H, F_OUT, false, false, true, false>
            <<<grid, 256, SMEM_64, s1>>>(h1, Bt2s, b2, nullptr, out, N2);
    }
    cudaEventRecord(evJ2, s1);

    {
        dim3 grid(TILES_N1, 1);
        gemm_kernel<64, 4, 2, F_H, F_OUT, false, false, true, true>
            <<<grid, 256, SMEM_64>>>(h1, Bt2n, zeros, nullptr, z2, N1);
    }
    cudaStreamWaitEvent(0, evJ2, 0);

    // --- 5. gather2 fused: out += mean(z2 over edges) ---
    gather2_fused_kernel<<<(N2 * 16 + 255) / 256, 256>>>(
        (const uint2*)z2, src1, rp1, (float4*)out);
}